// round 1
// baseline (speedup 1.0000x reference)
#include <cuda_runtime.h>
#include <cstddef>

#define BATCH 2
#define NSEQ  2048
#define DIM   1024
#define NH    16
#define DH    64
#define MTOK  (BATCH * NSEQ)   // 4096

// Scratch (allocation-free rule: __device__ globals)
__device__ float g_Q[BATCH * NH * DH * NSEQ];   // [b][h][d][q]   d-major
__device__ float g_K[BATCH * NH * DH * NSEQ];   // [b][h][d][kv]  d-major
__device__ float g_V[BATCH * NH * NSEQ * DH];   // [b][h][kv][d]
__device__ float g_A[BATCH * NSEQ * DIM];       // attention out, [b][q][h*64+d]

// ---------------------------------------------------------------------------
// C = A @ W^T   A:[M,K] row-major, W:[N,K] row-major.  M=4096, N=K=1024.
// LAYOUT 0: C[m*N+n] + bias[n]          (final output)
// LAYOUT 1: C[((b*NH+h)*DH+d)*NSEQ + s] (Q/K d-major)
// LAYOUT 2: C[((b*NH+h)*NSEQ+s)*DH + d] (V)
// 128x128 tile, BK=16, 256 threads, 8x8 per thread.
// ---------------------------------------------------------------------------
template <int LAYOUT>
__global__ __launch_bounds__(256)
void sgemm_abt(const float* __restrict__ A, const float* __restrict__ W,
               const float* __restrict__ bias, float* __restrict__ C)
{
    const int K = DIM;
    __shared__ float As[16][128];
    __shared__ float Bs[16][128];

    const int tid = threadIdx.x;
    const int tx = tid & 15, ty = tid >> 4;
    const int m0 = blockIdx.y * 128, n0 = blockIdx.x * 128;
    const int lrow = tid >> 2;          // 0..63
    const int lk   = (tid & 3) << 2;    // 0,4,8,12

    const float* Ap = A + (size_t)(m0 + lrow) * K + lk;
    const float* Wp = W + (size_t)(n0 + lrow) * K + lk;

    float acc[8][8];
#pragma unroll
    for (int i = 0; i < 8; i++)
#pragma unroll
        for (int j = 0; j < 8; j++) acc[i][j] = 0.f;

    for (int kt = 0; kt < K; kt += 16) {
        float4 a0 = *(const float4*)(Ap + kt);
        float4 a1 = *(const float4*)(Ap + (size_t)64 * K + kt);
        float4 b0 = *(const float4*)(Wp + kt);
        float4 b1 = *(const float4*)(Wp + (size_t)64 * K + kt);
        __syncthreads();
        As[lk + 0][lrow] = a0.x; As[lk + 1][lrow] = a0.y;
        As[lk + 2][lrow] = a0.z; As[lk + 3][lrow] = a0.w;
        As[lk + 0][lrow + 64] = a1.x; As[lk + 1][lrow + 64] = a1.y;
        As[lk + 2][lrow + 64] = a1.z; As[lk + 3][lrow + 64] = a1.w;
        Bs[lk + 0][lrow] = b0.x; Bs[lk + 1][lrow] = b0.y;
        Bs[lk + 2][lrow] = b0.z; Bs[lk + 3][lrow] = b0.w;
        Bs[lk + 0][lrow + 64] = b1.x; Bs[lk + 1][lrow + 64] = b1.y;
        Bs[lk + 2][lrow + 64] = b1.z; Bs[lk + 3][lrow + 64] = b1.w;
        __syncthreads();
#pragma unroll
        for (int k = 0; k < 16; k++) {
            float4 av0 = *(const float4*)&As[k][ty * 8];
            float4 av1 = *(const float4*)&As[k][ty * 8 + 4];
            float4 bv0 = *(const float4*)&Bs[k][tx * 8];
            float4 bv1 = *(const float4*)&Bs[k][tx * 8 + 4];
            float a[8] = {av0.x, av0.y, av0.z, av0.w, av1.x, av1.y, av1.z, av1.w};
            float b[8] = {bv0.x, bv0.y, bv0.z, bv0.w, bv1.x, bv1.y, bv1.z, bv1.w};
#pragma unroll
            for (int i = 0; i < 8; i++)
#pragma unroll
                for (int j = 0; j < 8; j++) acc[i][j] += a[i] * b[j];
        }
    }

    if (LAYOUT == 0) {
#pragma unroll
        for (int i = 0; i < 8; i++) {
            size_t base = (size_t)(m0 + ty * 8 + i) * DIM + n0 + tx * 8;
#pragma unroll
            for (int jj = 0; jj < 2; jj++) {
                int j0 = jj * 4;
                float4 v = make_float4(acc[i][j0 + 0] + bias[n0 + tx * 8 + j0 + 0],
                                       acc[i][j0 + 1] + bias[n0 + tx * 8 + j0 + 1],
                                       acc[i][j0 + 2] + bias[n0 + tx * 8 + j0 + 2],
                                       acc[i][j0 + 3] + bias[n0 + tx * 8 + j0 + 3]);
                *(float4*)&C[base + j0] = v;
            }
        }
    } else if (LAYOUT == 1) {
        // tile lives in one batch: NSEQ % 128 == 0
        const int b = m0 >> 11;
        const int s0 = (m0 & (NSEQ - 1)) + ty * 8;
#pragma unroll
        for (int j = 0; j < 8; j++) {
            int n = n0 + tx * 8 + j;
            int h = n >> 6, d = n & 63;
            size_t base = ((size_t)(b * NH + h) * DH + d) * NSEQ + s0;
            *(float4*)&C[base]     = make_float4(acc[0][j], acc[1][j], acc[2][j], acc[3][j]);
            *(float4*)&C[base + 4] = make_float4(acc[4][j], acc[5][j], acc[6][j], acc[7][j]);
        }
    } else {
        const int nb = n0 + tx * 8;
        const int h = nb >> 6, d0 = nb & 63;   // 8 cols stay inside one head (nb%64<=56)
#pragma unroll
        for (int i = 0; i < 8; i++) {
            int m = m0 + ty * 8 + i;
            int b = m >> 11, s = m & (NSEQ - 1);
            size_t base = ((size_t)(b * NH + h) * NSEQ + s) * DH + d0;
            *(float4*)&C[base]     = make_float4(acc[i][0], acc[i][1], acc[i][2], acc[i][3]);
            *(float4*)&C[base + 4] = make_float4(acc[i][4], acc[i][5], acc[i][6], acc[i][7]);
        }
    }
}

// ---------------------------------------------------------------------------
// Flash attention, fp32. Bq=64, Bk=64, Dh=64. 256 threads (16x16), each
// owns a 4q x 4k score fragment and 4q x 4d output fragment.
// Q,K come in d-major [bh][d][n]; V in [bh][kv][d]. Output -> [b][q][h*64+d].
// ---------------------------------------------------------------------------
__global__ __launch_bounds__(256)
void attn_kernel(const float* __restrict__ Qg, const float* __restrict__ Kg,
                 const float* __restrict__ Vg, const int* __restrict__ mask,
                 float* __restrict__ Og)
{
    extern __shared__ float sm[];
    float* Qs = sm;            // [64 d][64 q]
    float* Ks = sm + 4096;     // [64 d][64 k]
    float* Vs = sm + 8192;     // [64 k][64 d]
    float* Ps = sm + 12288;    // [64 q][64 k]
    int*   mk = (int*)(sm + 16384);

    const int tid = threadIdx.x;
    const int tx = tid & 15, ty = tid >> 4;
    const int bh = blockIdx.y;
    const int b = bh >> 4, h = bh & 15;
    const int q0 = blockIdx.x * 64;

    {   // load Q tile (coalesced: rows of 64 floats)
        int r = tid >> 4;
        int c = (tid & 15) * 4;
#pragma unroll
        for (int p = 0; p < 4; p++) {
            int rr = r + p * 16;
            *(float4*)&Qs[rr * 64 + c] =
                *(const float4*)&Qg[((size_t)bh * DH + rr) * NSEQ + q0 + c];
        }
    }

    float m_[4], l_[4], o_[4][4];
#pragma unroll
    for (int i = 0; i < 4; i++) {
        m_[i] = -1e30f; l_[i] = 0.f;
#pragma unroll
        for (int j = 0; j < 4; j++) o_[i][j] = 0.f;
    }

    for (int t = 0; t < NSEQ / 64; t++) {
        const int kv0 = t * 64;
        __syncthreads();   // previous tile's Vs/Ps reads done; Qs visible after next sync
        {
            int r = tid >> 4;
            int c = (tid & 15) * 4;
#pragma unroll
            for (int p = 0; p < 4; p++) {
                int rr = r + p * 16;
                *(float4*)&Ks[rr * 64 + c] =
                    *(const float4*)&Kg[((size_t)bh * DH + rr) * NSEQ + kv0 + c];
                *(float4*)&Vs[rr * 64 + c] =
                    *(const float4*)&Vg[((size_t)bh * NSEQ + kv0 + rr) * DH + c];
            }
            if (tid < 64) mk[tid] = mask[b * NSEQ + kv0 + tid];
        }
        __syncthreads();

        float s[4][4];
#pragma unroll
        for (int i = 0; i < 4; i++)
#pragma unroll
            for (int j = 0; j < 4; j++) s[i][j] = 0.f;

#pragma unroll 8
        for (int d = 0; d < 64; d++) {
            float4 qv = *(const float4*)&Qs[d * 64 + ty * 4];
            float4 kv = *(const float4*)&Ks[d * 64 + tx * 4];
            float qa[4] = {qv.x, qv.y, qv.z, qv.w};
            float ka[4] = {kv.x, kv.y, kv.z, kv.w};
#pragma unroll
            for (int i = 0; i < 4; i++)
#pragma unroll
                for (int j = 0; j < 4; j++) s[i][j] += qa[i] * ka[j];
        }

        int mv[4];
#pragma unroll
        for (int j = 0; j < 4; j++) mv[j] = mk[tx * 4 + j];
#pragma unroll
        for (int i = 0; i < 4; i++)
#pragma unroll
            for (int j = 0; j < 4; j++)
                s[i][j] = mv[j] ? s[i][j] * 0.125f : -1e9f;

        // online softmax (reduce across the 16 lanes that share a query row)
#pragma unroll
        for (int i = 0; i < 4; i++) {
            float rm = fmaxf(fmaxf(s[i][0], s[i][1]), fmaxf(s[i][2], s[i][3]));
#pragma unroll
            for (int off = 8; off >= 1; off >>= 1)
                rm = fmaxf(rm, __shfl_xor_sync(0xffffffffu, rm, off));
            float mn = fmaxf(m_[i], rm);
            float alpha = __expf(m_[i] - mn);
            float rs = 0.f;
#pragma unroll
            for (int j = 0; j < 4; j++) {
                float p = __expf(s[i][j] - mn);
                s[i][j] = p; rs += p;
            }
#pragma unroll
            for (int off = 8; off >= 1; off >>= 1)
                rs += __shfl_xor_sync(0xffffffffu, rs, off);
            l_[i] = l_[i] * alpha + rs;
            m_[i] = mn;
#pragma unroll
            for (int j = 0; j < 4; j++) o_[i][j] *= alpha;
        }

#pragma unroll
        for (int i = 0; i < 4; i++)
            *(float4*)&Ps[(ty * 4 + i) * 64 + tx * 4] =
                make_float4(s[i][0], s[i][1], s[i][2], s[i][3]);
        __syncthreads();

        // O += P @ V
#pragma unroll 4
        for (int kk = 0; kk < 64; kk += 4) {
            float4 v0 = *(const float4*)&Vs[(kk + 0) * 64 + tx * 4];
            float4 v1 = *(const float4*)&Vs[(kk + 1) * 64 + tx * 4];
            float4 v2 = *(const float4*)&Vs[(kk + 2) * 64 + tx * 4];
            float4 v3 = *(const float4*)&Vs[(kk + 3) * 64 + tx * 4];
#pragma unroll
            for (int i = 0; i < 4; i++) {
                float4 pv = *(const float4*)&Ps[(ty * 4 + i) * 64 + kk];
                o_[i][0] += pv.x * v0.x + pv.y * v1.x + pv.z * v2.x + pv.w * v3.x;
                o_[i][1] += pv.x * v0.y + pv.y * v1.y + pv.z * v2.y + pv.w * v3.y;
                o_[i][2] += pv.x * v0.z + pv.y * v1.z + pv.z * v2.z + pv.w * v3.z;
                o_[i][3] += pv.x * v0.w + pv.y * v1.w + pv.z * v2.w + pv.w * v3.w;
            }
        }
    }

#pragma unroll
    for (int i = 0; i < 4; i++) {
        float inv = 1.f / l_[i];
        int q = q0 + ty * 4 + i;
        float4 ov = make_float4(o_[i][0] * inv, o_[i][1] * inv,
                                o_[i][2] * inv, o_[i][3] * inv);
        *(float4*)&Og[(size_t)(b * NSEQ + q) * DIM + h * DH + tx * 4] = ov;
    }
}

// ---------------------------------------------------------------------------
extern "C" void kernel_launch(void* const* d_in, const int* in_sizes, int n_in,
                              void* d_out, int out_size)
{
    const float* x1 = (const float*)d_in[0];   // feat1_query
    const float* x2 = (const float*)d_in[1];   // feat2_key_value
    const float* Wq = (const float*)d_in[2];
    const float* Wk = (const float*)d_in[3];
    const float* Wv = (const float*)d_in[4];
    const float* Wo = (const float*)d_in[5];
    const float* bo = (const float*)d_in[6];
    const int*   mk = (const int*)d_in[7];
    float* out = (float*)d_out;

    float *q, *k, *v, *a;
    cudaGetSymbolAddress((void**)&q, g_Q);
    cudaGetSymbolAddress((void**)&k, g_K);
    cudaGetSymbolAddress((void**)&v, g_V);
    cudaGetSymbolAddress((void**)&a, g_A);

    const dim3 gg(DIM / 128, MTOK / 128);   // (8, 32)
    sgemm_abt<1><<<gg, 256>>>(x1, Wq, nullptr, q);
    sgemm_abt<1><<<gg, 256>>>(x2, Wk, nullptr, k);
    sgemm_abt<2><<<gg, 256>>>(x2, Wv, nullptr, v);

    const int smem_bytes = (4 * 64 * 64) * (int)sizeof(float) + 64 * (int)sizeof(int);
    cudaFuncSetAttribute(attn_kernel, cudaFuncAttributeMaxDynamicSharedMemorySize, smem_bytes);
    attn_kernel<<<dim3(NSEQ / 64, BATCH * NH), 256, smem_bytes>>>(q, k, v, mk, a);

    sgemm_abt<0><<<gg, 256>>>(a, Wo, bo, out);
}

// round 3
// speedup vs baseline: 1.7214x; 1.7214x over previous
#include <cuda_runtime.h>
#include <cstddef>
#include <cstdint>

#define BATCH 2
#define NSEQ  2048
#define DIM   1024
#define NH    16
#define DH    64
#define MTOK  (BATCH * NSEQ)   // 4096

// Scratch (allocation-free rule: __device__ globals). All [bh][s][d] layout.
__device__ float g_Q[BATCH * NH * NSEQ * DH];   // tf32 bits, pre-scaled by 1/8
__device__ float g_K[BATCH * NH * NSEQ * DH];   // tf32 bits
__device__ float g_V[BATCH * NH * NSEQ * DH];   // tf32 bits
__device__ float g_A[BATCH * NSEQ * DIM];       // attention out fp32, [b][q][h*64+d]

// ---------------------------------------------------------------------------
__device__ __forceinline__ uint32_t f2tf32(float x) {
    uint32_t y;
    asm("cvt.rna.tf32.f32 %0, %1;" : "=r"(y) : "f"(x));
    return y;
}

// D += A * B, m16n8k8 tf32 (A row-major 16x8, B col-major 8x8)
__device__ __forceinline__ void mma8(float* d, const uint32_t* a, const uint32_t* b) {
    asm volatile(
        "mma.sync.aligned.m16n8k8.row.col.f32.tf32.tf32.f32 "
        "{%0,%1,%2,%3}, {%4,%5,%6,%7}, {%8,%9}, {%0,%1,%2,%3};"
        : "+f"(d[0]), "+f"(d[1]), "+f"(d[2]), "+f"(d[3])
        : "r"(a[0]), "r"(a[1]), "r"(a[2]), "r"(a[3]), "r"(b[0]), "r"(b[1]));
}

// ---------------------------------------------------------------------------
// tf32 tensor-core GEMM: C = A @ W^T. A:[M,K] row-major, W:[N,K] row-major.
// M=4096, N=K=1024. Block 128x128, BK=16 double-buffered, 8 warps (32x64 each).
// LAYOUT 0: C[m*DIM+n] = acc + bias[n]                       (fp32 out)
// LAYOUT 2: C[((b*NH+h)*NSEQ+s)*DH+d] = tf32(acc * scale)    (QKV scratch)
// ---------------------------------------------------------------------------
template <int LAYOUT>
__global__ __launch_bounds__(256)
void tgemm(const float* __restrict__ A, const float* __restrict__ W,
           const float* __restrict__ bias, float* __restrict__ C, float scale)
{
    __shared__ float As[2][128][20];
    __shared__ float Bs[2][128][20];

    const int tid = threadIdx.x;
    const int lane = tid & 31, wid = tid >> 5;
    const int g = lane >> 2, tq = lane & 3;
    const int wm = (wid & 3) * 32, wn = (wid >> 2) * 64;
    const int m0 = blockIdx.y * 128, n0 = blockIdx.x * 128;

    const int lr = tid >> 1;             // 0..127
    const int lc = (tid & 1) * 8;        // 0 or 8
    const float* Ap = A + (size_t)(m0 + lr) * DIM + lc;
    const float* Wp = W + (size_t)(n0 + lr) * DIM + lc;

    float acc[2][8][4];
#pragma unroll
    for (int mt = 0; mt < 2; mt++)
#pragma unroll
        for (int nt = 0; nt < 8; nt++)
#pragma unroll
            for (int c = 0; c < 4; c++) acc[mt][nt][c] = 0.f;

    // load k-chunk 0 into buffer 0
    {
        float4 a0 = *(const float4*)Ap,       a1 = *(const float4*)(Ap + 4);
        float4 b0 = *(const float4*)Wp,       b1 = *(const float4*)(Wp + 4);
        float av[8] = {a0.x,a0.y,a0.z,a0.w,a1.x,a1.y,a1.z,a1.w};
        float bv[8] = {b0.x,b0.y,b0.z,b0.w,b1.x,b1.y,b1.z,b1.w};
#pragma unroll
        for (int i = 0; i < 8; i++) {
            As[0][lr][lc + i] = __uint_as_float(f2tf32(av[i]));
            Bs[0][lr][lc + i] = __uint_as_float(f2tf32(bv[i]));
        }
    }
    __syncthreads();

    for (int kt = 0; kt < 64; kt++) {
        const int cur = kt & 1;
        float4 pa0, pa1, pb0, pb1;
        if (kt < 63) {
            const float* s1 = Ap + (kt + 1) * 16;
            const float* s2 = Wp + (kt + 1) * 16;
            pa0 = *(const float4*)s1; pa1 = *(const float4*)(s1 + 4);
            pb0 = *(const float4*)s2; pb1 = *(const float4*)(s2 + 4);
        }
#pragma unroll
        for (int kc = 0; kc < 2; kc++) {
            const int k0 = kc * 8;
            uint32_t af[2][4], bf[8][2];
#pragma unroll
            for (int mt = 0; mt < 2; mt++) {
                const int mb = wm + mt * 16;
                af[mt][0] = __float_as_uint(As[cur][mb + g    ][k0 + tq    ]);
                af[mt][1] = __float_as_uint(As[cur][mb + g + 8][k0 + tq    ]);
                af[mt][2] = __float_as_uint(As[cur][mb + g    ][k0 + tq + 4]);
                af[mt][3] = __float_as_uint(As[cur][mb + g + 8][k0 + tq + 4]);
            }
#pragma unroll
            for (int nt = 0; nt < 8; nt++) {
                const int nb = wn + nt * 8;
                bf[nt][0] = __float_as_uint(Bs[cur][nb + g][k0 + tq    ]);
                bf[nt][1] = __float_as_uint(Bs[cur][nb + g][k0 + tq + 4]);
            }
#pragma unroll
            for (int mt = 0; mt < 2; mt++)
#pragma unroll
                for (int nt = 0; nt < 8; nt++)
                    mma8(acc[mt][nt], af[mt], bf[nt]);
        }
        if (kt < 63) {
            float av[8] = {pa0.x,pa0.y,pa0.z,pa0.w,pa1.x,pa1.y,pa1.z,pa1.w};
            float bv[8] = {pb0.x,pb0.y,pb0.z,pb0.w,pb1.x,pb1.y,pb1.z,pb1.w};
#pragma unroll
            for (int i = 0; i < 8; i++) {
                As[cur ^ 1][lr][lc + i] = __uint_as_float(f2tf32(av[i]));
                Bs[cur ^ 1][lr][lc + i] = __uint_as_float(f2tf32(bv[i]));
            }
        }
        __syncthreads();
    }

    // epilogue
#pragma unroll
    for (int mt = 0; mt < 2; mt++) {
        const int r0 = m0 + wm + mt * 16 + g;
        const int r1 = r0 + 8;
#pragma unroll
        for (int nt = 0; nt < 8; nt++) {
            const int n = n0 + wn + nt * 8 + tq * 2;
            if (LAYOUT == 0) {
                const float b0v = bias[n], b1v = bias[n + 1];
                float2 v0 = make_float2(acc[mt][nt][0] + b0v, acc[mt][nt][1] + b1v);
                float2 v1 = make_float2(acc[mt][nt][2] + b0v, acc[mt][nt][3] + b1v);
                *(float2*)&C[(size_t)r0 * DIM + n] = v0;
                *(float2*)&C[(size_t)r1 * DIM + n] = v1;
            } else {
                const int h = n >> 6, d = n & 63;
                const int b0i = r0 >> 11, s0 = r0 & (NSEQ - 1);
                const int b1i = r1 >> 11, s1 = r1 & (NSEQ - 1);
                float2 v0 = make_float2(
                    __uint_as_float(f2tf32(acc[mt][nt][0] * scale)),
                    __uint_as_float(f2tf32(acc[mt][nt][1] * scale)));
                float2 v1 = make_float2(
                    __uint_as_float(f2tf32(acc[mt][nt][2] * scale)),
                    __uint_as_float(f2tf32(acc[mt][nt][3] * scale)));
                *(float2*)&C[((size_t)(b0i * NH + h) * NSEQ + s0) * DH + d] = v0;
                *(float2*)&C[((size_t)(b1i * NH + h) * NSEQ + s1) * DH + d] = v1;
            }
        }
    }
}

// ---------------------------------------------------------------------------
// Flash attention on tensor cores. Bq=64 (4 warps x 16 rows), Bk=64, Dh=64.
// Q pre-scaled by 1/8, Q/K/V already tf32 bits in [bh][s][d].
// ---------------------------------------------------------------------------
#define QS 0
#define KS 4352            // 64*68
#define VS 8704            // + 64*68
#define PS 13312           // + 64*72
#define MK 17664           // + 64*68
#define ATTN_SMEM_BYTES (17664 * 4 + 64 * 4)

__global__ __launch_bounds__(128)
void attn_kernel(const float* __restrict__ Qg, const float* __restrict__ Kg,
                 const float* __restrict__ Vg, const int* __restrict__ mask,
                 float* __restrict__ Og)
{
    extern __shared__ float sm[];
    float* Qs = sm + QS;    // [64][68]
    float* Ks = sm + KS;    // [64][68]
    float* Vs = sm + VS;    // [64][72]
    float* Ps = sm + PS;    // [64][68]
    int*   mk = (int*)(sm + MK);

    const int tid = threadIdx.x;
    const int lane = tid & 31, w = tid >> 5;
    const int g = lane >> 2, tq = lane & 3;
    const int bh = blockIdx.y;
    const int b = bh >> 4, h = bh & 15;
    const int q0 = blockIdx.x * 64;
    const int mb = w * 16;

    // load Q tile: 64 rows x 64 floats, 2 threads per row
    {
        const int r = tid >> 1, c = (tid & 1) * 32;
        const float* src = Qg + ((size_t)bh * NSEQ + q0 + r) * DH + c;
#pragma unroll
        for (int i = 0; i < 8; i++)
            *(float4*)&Qs[r * 68 + c + i * 4] = *(const float4*)(src + i * 4);
    }

    float m0_ = -1e30f, m1_ = -1e30f, l0_ = 0.f, l1_ = 0.f;
    float o[8][4];
#pragma unroll
    for (int nt = 0; nt < 8; nt++)
#pragma unroll
        for (int c = 0; c < 4; c++) o[nt][c] = 0.f;

    for (int t = 0; t < NSEQ / 64; t++) {
        const int kv0 = t * 64;
        __syncthreads();
        {
            const int r = tid >> 1, c = (tid & 1) * 32;
            const float* ks = Kg + ((size_t)bh * NSEQ + kv0 + r) * DH + c;
            const float* vs = Vg + ((size_t)bh * NSEQ + kv0 + r) * DH + c;
#pragma unroll
            for (int i = 0; i < 8; i++) {
                *(float4*)&Ks[r * 68 + c + i * 4] = *(const float4*)(ks + i * 4);
                *(float4*)&Vs[r * 72 + c + i * 4] = *(const float4*)(vs + i * 4);
            }
            if (tid < 64) mk[tid] = mask[b * NSEQ + kv0 + tid];
        }
        __syncthreads();

        // S = Q @ K^T  (16 q-rows per warp x 64 kv)
        float s[8][4];
#pragma unroll
        for (int nt = 0; nt < 8; nt++)
#pragma unroll
            for (int c = 0; c < 4; c++) s[nt][c] = 0.f;

#pragma unroll
        for (int kc = 0; kc < 8; kc++) {
            const int k0 = kc * 8;
            uint32_t af[4], bf[8][2];
            af[0] = __float_as_uint(Qs[(mb + g    ) * 68 + k0 + tq    ]);
            af[1] = __float_as_uint(Qs[(mb + g + 8) * 68 + k0 + tq    ]);
            af[2] = __float_as_uint(Qs[(mb + g    ) * 68 + k0 + tq + 4]);
            af[3] = __float_as_uint(Qs[(mb + g + 8) * 68 + k0 + tq + 4]);
#pragma unroll
            for (int nt = 0; nt < 8; nt++) {
                bf[nt][0] = __float_as_uint(Ks[(nt * 8 + g) * 68 + k0 + tq    ]);
                bf[nt][1] = __float_as_uint(Ks[(nt * 8 + g) * 68 + k0 + tq + 4]);
            }
#pragma unroll
            for (int nt = 0; nt < 8; nt++) mma8(s[nt], af, bf[nt]);
        }

        // mask (per kv column)
#pragma unroll
        for (int nt = 0; nt < 8; nt++) {
            const int j = nt * 8 + tq * 2;
            const int mv0 = mk[j], mv1 = mk[j + 1];
            if (!mv0) { s[nt][0] = -1e9f; s[nt][2] = -1e9f; }
            if (!mv1) { s[nt][1] = -1e9f; s[nt][3] = -1e9f; }
        }

        // online softmax over 2 rows (g and g+8); reduce across 4 lanes/group
        float rm0 = -1e30f, rm1 = -1e30f;
#pragma unroll
        for (int nt = 0; nt < 8; nt++) {
            rm0 = fmaxf(rm0, fmaxf(s[nt][0], s[nt][1]));
            rm1 = fmaxf(rm1, fmaxf(s[nt][2], s[nt][3]));
        }
        rm0 = fmaxf(rm0, __shfl_xor_sync(0xffffffffu, rm0, 1));
        rm0 = fmaxf(rm0, __shfl_xor_sync(0xffffffffu, rm0, 2));
        rm1 = fmaxf(rm1, __shfl_xor_sync(0xffffffffu, rm1, 1));
        rm1 = fmaxf(rm1, __shfl_xor_sync(0xffffffffu, rm1, 2));
        const float mn0 = fmaxf(m0_, rm0), mn1 = fmaxf(m1_, rm1);
        const float al0 = __expf(m0_ - mn0), al1 = __expf(m1_ - mn1);
        float rs0 = 0.f, rs1 = 0.f;
#pragma unroll
        for (int nt = 0; nt < 8; nt++) {
            s[nt][0] = __expf(s[nt][0] - mn0);
            s[nt][1] = __expf(s[nt][1] - mn0);
            s[nt][2] = __expf(s[nt][2] - mn1);
            s[nt][3] = __expf(s[nt][3] - mn1);
            rs0 += s[nt][0] + s[nt][1];
            rs1 += s[nt][2] + s[nt][3];
        }
        rs0 += __shfl_xor_sync(0xffffffffu, rs0, 1);
        rs0 += __shfl_xor_sync(0xffffffffu, rs0, 2);
        rs1 += __shfl_xor_sync(0xffffffffu, rs1, 1);
        rs1 += __shfl_xor_sync(0xffffffffu, rs1, 2);
        l0_ = l0_ * al0 + rs0;  m0_ = mn0;
        l1_ = l1_ * al1 + rs1;  m1_ = mn1;
#pragma unroll
        for (int nt = 0; nt < 8; nt++) {
            o[nt][0] *= al0; o[nt][1] *= al0;
            o[nt][2] *= al1; o[nt][3] *= al1;
        }

        // write P (tf32) to smem; own rows only
#pragma unroll
        for (int nt = 0; nt < 8; nt++) {
            const int j = nt * 8 + tq * 2;
            float2 p0 = make_float2(__uint_as_float(f2tf32(s[nt][0])),
                                    __uint_as_float(f2tf32(s[nt][1])));
            float2 p1 = make_float2(__uint_as_float(f2tf32(s[nt][2])),
                                    __uint_as_float(f2tf32(s[nt][3])));
            *(float2*)&Ps[(mb + g    ) * 68 + j] = p0;
            *(float2*)&Ps[(mb + g + 8) * 68 + j] = p1;
        }
        __syncwarp();

        // O += P @ V   (k = 64 kv, n = 64 d)
#pragma unroll
        for (int kc = 0; kc < 8; kc++) {
            const int k0 = kc * 8;
            uint32_t af[4], bf[8][2];
            af[0] = __float_as_uint(Ps[(mb + g    ) * 68 + k0 + tq    ]);
            af[1] = __float_as_uint(Ps[(mb + g + 8) * 68 + k0 + tq    ]);
            af[2] = __float_as_uint(Ps[(mb + g    ) * 68 + k0 + tq + 4]);
            af[3] = __float_as_uint(Ps[(mb + g + 8) * 68 + k0 + tq + 4]);
#pragma unroll
            for (int nt = 0; nt < 8; nt++) {
                bf[nt][0] = __float_as_uint(Vs[(k0 + tq    ) * 72 + nt * 8 + g]);
                bf[nt][1] = __float_as_uint(Vs[(k0 + tq + 4) * 72 + nt * 8 + g]);
            }
#pragma unroll
            for (int nt = 0; nt < 8; nt++) mma8(o[nt], af, bf[nt]);
        }
    }

    // final normalize + store
    const float inv0 = 1.f / l0_, inv1 = 1.f / l1_;
    const int qr0 = q0 + mb + g, qr1 = qr0 + 8;
#pragma unroll
    for (int nt = 0; nt < 8; nt++) {
        const int d = nt * 8 + tq * 2;
        float2 v0 = make_float2(o[nt][0] * inv0, o[nt][1] * inv0);
        float2 v1 = make_float2(o[nt][2] * inv1, o[nt][3] * inv1);
        *(float2*)&Og[(size_t)(b * NSEQ + qr0) * DIM + h * DH + d] = v0;
        *(float2*)&Og[(size_t)(b * NSEQ + qr1) * DIM + h * DH + d] = v1;
    }
}

// ---------------------------------------------------------------------------
extern "C" void kernel_launch(void* const* d_in, const int* in_sizes, int n_in,
                              void* d_out, int out_size)
{
    const float* x1 = (const float*)d_in[0];   // feat1_query
    const float* x2 = (const float*)d_in[1];   // feat2_key_value
    const float* Wq = (const float*)d_in[2];
    const float* Wk = (const float*)d_in[3];
    const float* Wv = (const float*)d_in[4];
    const float* Wo = (const float*)d_in[5];
    const float* bo = (const float*)d_in[6];
    const int*   mk = (const int*)d_in[7];
    float* out = (float*)d_out;

    float *q, *k, *v, *a;
    cudaGetSymbolAddress((void**)&q, g_Q);
    cudaGetSymbolAddress((void**)&k, g_K);
    cudaGetSymbolAddress((void**)&v, g_V);
    cudaGetSymbolAddress((void**)&a, g_A);

    const dim3 gg(DIM / 128, MTOK / 128);   // (8, 32)
    tgemm<2><<<gg, 256>>>(x1, Wq, nullptr, q, 0.125f);
    tgemm<2><<<gg, 256>>>(x2, Wk, nullptr, k, 1.0f);
    tgemm<2><<<gg, 256>>>(x2, Wv, nullptr, v, 1.0f);

    cudaFuncSetAttribute(attn_kernel, cudaFuncAttributeMaxDynamicSharedMemorySize,
                         ATTN_SMEM_BYTES);
    attn_kernel<<<dim3(NSEQ / 64, BATCH * NH), 128, ATTN_SMEM_BYTES>>>(q, k, v, mk, a);

    tgemm<0><<<gg, 256>>>(a, Wo, bo, out, 1.0f);
}

// round 4
// speedup vs baseline: 2.4287x; 1.4109x over previous
#include <cuda_runtime.h>
#include <cstddef>
#include <cstdint>

#define BATCH 2
#define NSEQ  2048
#define DIM   1024
#define NH    16
#define DH    64
#define MTOK  (BATCH * NSEQ)   // 4096

// Scratch (allocation-free rule: __device__ globals). All [bh][s][d] layout.
__device__ float g_Q[BATCH * NH * NSEQ * DH];   // tf32 bits, pre-scaled by 1/8
__device__ float g_K[BATCH * NH * NSEQ * DH];   // tf32 bits
__device__ float g_V[BATCH * NH * NSEQ * DH];   // tf32 bits
__device__ float g_A[BATCH * NSEQ * DIM];       // attention out fp32, [b][q][h*64+d]

// ---------------------------------------------------------------------------
__device__ __forceinline__ uint32_t f2tf32(float x) {
    uint32_t y;
    asm("cvt.rna.tf32.f32 %0, %1;" : "=r"(y) : "f"(x));
    return y;
}

// D += A * B, m16n8k8 tf32 (A row-major 16x8, B col-major 8x8)
__device__ __forceinline__ void mma8(float* d, const uint32_t* a, const uint32_t* b) {
    asm volatile(
        "mma.sync.aligned.m16n8k8.row.col.f32.tf32.tf32.f32 "
        "{%0,%1,%2,%3}, {%4,%5,%6,%7}, {%8,%9}, {%0,%1,%2,%3};"
        : "+f"(d[0]), "+f"(d[1]), "+f"(d[2]), "+f"(d[3])
        : "r"(a[0]), "r"(a[1]), "r"(a[2]), "r"(a[3]), "r"(b[0]), "r"(b[1]));
}

// ---------------------------------------------------------------------------
// tf32 tensor-core GEMM: C = A @ W^T. A:[M,K] row-major, W:[N,K] row-major.
// M=4096, N=K=1024. Block 128x128, BK=16 double-buffered, 8 warps (32x64 each).
// LAYOUT 0: C[m*DIM+n] = acc + bias[n]                       (fp32 out)
// LAYOUT 2: C[((b*NH+h)*NSEQ+s)*DH+d] = tf32(acc * scale)    (QKV scratch)
// ---------------------------------------------------------------------------
template <int LAYOUT>
__global__ __launch_bounds__(256)
void tgemm(const float* __restrict__ A, const float* __restrict__ W,
           const float* __restrict__ bias, float* __restrict__ C, float scale)
{
    __shared__ float As[2][128][20];
    __shared__ float Bs[2][128][20];

    const int tid = threadIdx.x;
    const int lane = tid & 31, wid = tid >> 5;
    const int g = lane >> 2, tq = lane & 3;
    const int wm = (wid & 3) * 32, wn = (wid >> 2) * 64;
    const int m0 = blockIdx.y * 128, n0 = blockIdx.x * 128;

    const int lr = tid >> 1;             // 0..127
    const int lc = (tid & 1) * 8;        // 0 or 8
    const float* Ap = A + (size_t)(m0 + lr) * DIM + lc;
    const float* Wp = W + (size_t)(n0 + lr) * DIM + lc;

    float acc[2][8][4];
#pragma unroll
    for (int mt = 0; mt < 2; mt++)
#pragma unroll
        for (int nt = 0; nt < 8; nt++)
#pragma unroll
            for (int c = 0; c < 4; c++) acc[mt][nt][c] = 0.f;

    {
        float4 a0 = *(const float4*)Ap,       a1 = *(const float4*)(Ap + 4);
        float4 b0 = *(const float4*)Wp,       b1 = *(const float4*)(Wp + 4);
        float av[8] = {a0.x,a0.y,a0.z,a0.w,a1.x,a1.y,a1.z,a1.w};
        float bv[8] = {b0.x,b0.y,b0.z,b0.w,b1.x,b1.y,b1.z,b1.w};
#pragma unroll
        for (int i = 0; i < 8; i++) {
            As[0][lr][lc + i] = __uint_as_float(f2tf32(av[i]));
            Bs[0][lr][lc + i] = __uint_as_float(f2tf32(bv[i]));
        }
    }
    __syncthreads();

    for (int kt = 0; kt < 64; kt++) {
        const int cur = kt & 1;
        float4 pa0, pa1, pb0, pb1;
        if (kt < 63) {
            const float* s1 = Ap + (kt + 1) * 16;
            const float* s2 = Wp + (kt + 1) * 16;
            pa0 = *(const float4*)s1; pa1 = *(const float4*)(s1 + 4);
            pb0 = *(const float4*)s2; pb1 = *(const float4*)(s2 + 4);
        }
#pragma unroll
        for (int kc = 0; kc < 2; kc++) {
            const int k0 = kc * 8;
            uint32_t af[2][4], bf[8][2];
#pragma unroll
            for (int mt = 0; mt < 2; mt++) {
                const int mb = wm + mt * 16;
                af[mt][0] = __float_as_uint(As[cur][mb + g    ][k0 + tq    ]);
                af[mt][1] = __float_as_uint(As[cur][mb + g + 8][k0 + tq    ]);
                af[mt][2] = __float_as_uint(As[cur][mb + g    ][k0 + tq + 4]);
                af[mt][3] = __float_as_uint(As[cur][mb + g + 8][k0 + tq + 4]);
            }
#pragma unroll
            for (int nt = 0; nt < 8; nt++) {
                const int nb = wn + nt * 8;
                bf[nt][0] = __float_as_uint(Bs[cur][nb + g][k0 + tq    ]);
                bf[nt][1] = __float_as_uint(Bs[cur][nb + g][k0 + tq + 4]);
            }
#pragma unroll
            for (int mt = 0; mt < 2; mt++)
#pragma unroll
                for (int nt = 0; nt < 8; nt++)
                    mma8(acc[mt][nt], af[mt], bf[nt]);
        }
        if (kt < 63) {
            float av[8] = {pa0.x,pa0.y,pa0.z,pa0.w,pa1.x,pa1.y,pa1.z,pa1.w};
            float bv[8] = {pb0.x,pb0.y,pb0.z,pb0.w,pb1.x,pb1.y,pb1.z,pb1.w};
#pragma unroll
            for (int i = 0; i < 8; i++) {
                As[cur ^ 1][lr][lc + i] = __uint_as_float(f2tf32(av[i]));
                Bs[cur ^ 1][lr][lc + i] = __uint_as_float(f2tf32(bv[i]));
            }
        }
        __syncthreads();
    }

#pragma unroll
    for (int mt = 0; mt < 2; mt++) {
        const int r0 = m0 + wm + mt * 16 + g;
        const int r1 = r0 + 8;
#pragma unroll
        for (int nt = 0; nt < 8; nt++) {
            const int n = n0 + wn + nt * 8 + tq * 2;
            if (LAYOUT == 0) {
                const float b0v = bias[n], b1v = bias[n + 1];
                float2 v0 = make_float2(acc[mt][nt][0] + b0v, acc[mt][nt][1] + b1v);
                float2 v1 = make_float2(acc[mt][nt][2] + b0v, acc[mt][nt][3] + b1v);
                *(float2*)&C[(size_t)r0 * DIM + n] = v0;
                *(float2*)&C[(size_t)r1 * DIM + n] = v1;
            } else {
                const int h = n >> 6, d = n & 63;
                const int b0i = r0 >> 11, s0 = r0 & (NSEQ - 1);
                const int b1i = r1 >> 11, s1 = r1 & (NSEQ - 1);
                float2 v0 = make_float2(
                    __uint_as_float(f2tf32(acc[mt][nt][0] * scale)),
                    __uint_as_float(f2tf32(acc[mt][nt][1] * scale)));
                float2 v1 = make_float2(
                    __uint_as_float(f2tf32(acc[mt][nt][2] * scale)),
                    __uint_as_float(f2tf32(acc[mt][nt][3] * scale)));
                *(float2*)&C[((size_t)(b0i * NH + h) * NSEQ + s0) * DH + d] = v0;
                *(float2*)&C[((size_t)(b1i * NH + h) * NSEQ + s1) * DH + d] = v1;
            }
        }
    }
}

// ---------------------------------------------------------------------------
// Flash attention on tensor cores. Bq=128 (4 warps x 2 m-tiles x 16 rows),
// Bk=64, Dh=64. Q pre-scaled by 1/8; Q/K/V tf32 bits in [bh][s][d].
// ---------------------------------------------------------------------------
#define AQ 0
#define AK 8704                 // Qs: 128*68
#define AV 13056                // Ks: 64*68
#define AP 17664                // Vs: 64*72
#define AM 26368                // Ps: 128*68
#define ATTN_SMEM_BYTES ((26368 + 64) * 4)

__global__ __launch_bounds__(128)
void attn_kernel(const float* __restrict__ Qg, const float* __restrict__ Kg,
                 const float* __restrict__ Vg, const int* __restrict__ mask,
                 float* __restrict__ Og)
{
    extern __shared__ float sm[];
    float* Qs = sm + AQ;    // [128][68]
    float* Ks = sm + AK;    // [64][68]
    float* Vs = sm + AV;    // [64][72]
    float* Ps = sm + AP;    // [128][68]
    int*   mk = (int*)(sm + AM);

    const int tid = threadIdx.x;
    const int lane = tid & 31, w = tid >> 5;
    const int g = lane >> 2, tq = lane & 3;
    const int bh = blockIdx.y;
    const int b = bh >> 4, h = bh & 15;
    const int q0 = blockIdx.x * 128;

    // stage Q tile (contiguous 128x64 block) into padded smem
    {
        const float* Qb = Qg + ((size_t)bh * NSEQ + q0) * DH;
#pragma unroll
        for (int it = 0; it < 16; it++) {
            int j = it * 128 + tid;                       // float4 index
            *(float4*)&Qs[(j >> 4) * 68 + (j & 15) * 4] = *(const float4*)(Qb + j * 4);
        }
    }

    const int rb[2] = { w * 32 + g, w * 32 + 16 + g };    // base rows per m-tile

    float m_[2][2], l_[2][2], o[2][8][4];
#pragma unroll
    for (int mt = 0; mt < 2; mt++) {
        m_[mt][0] = -1e30f; m_[mt][1] = -1e30f;
        l_[mt][0] = 0.f;    l_[mt][1] = 0.f;
#pragma unroll
        for (int nt = 0; nt < 8; nt++)
#pragma unroll
            for (int c = 0; c < 4; c++) o[mt][nt][c] = 0.f;
    }

    for (int t = 0; t < NSEQ / 64; t++) {
        const int kv0 = t * 64;
        __syncthreads();
        {
            const float* Kb = Kg + ((size_t)bh * NSEQ + kv0) * DH;
            const float* Vb = Vg + ((size_t)bh * NSEQ + kv0) * DH;
#pragma unroll
            for (int it = 0; it < 8; it++) {
                int j = it * 128 + tid;                   // float4 index (64*16)
                *(float4*)&Ks[(j >> 4) * 68 + (j & 15) * 4] = *(const float4*)(Kb + j * 4);
                *(float4*)&Vs[(j >> 4) * 72 + (j & 15) * 4] = *(const float4*)(Vb + j * 4);
            }
            if (tid < 64) mk[tid] = mask[b * NSEQ + kv0 + tid];
        }
        __syncthreads();

        // S = Q @ K^T  (2 x 16 q-rows per warp x 64 kv)
        float s[2][8][4];
#pragma unroll
        for (int mt = 0; mt < 2; mt++)
#pragma unroll
            for (int nt = 0; nt < 8; nt++)
#pragma unroll
                for (int c = 0; c < 4; c++) s[mt][nt][c] = 0.f;

#pragma unroll
        for (int kc = 0; kc < 8; kc++) {
            const int k0 = kc * 8;
            uint32_t af[2][4], bf[8][2];
#pragma unroll
            for (int mt = 0; mt < 2; mt++) {
                af[mt][0] = __float_as_uint(Qs[(rb[mt]    ) * 68 + k0 + tq    ]);
                af[mt][1] = __float_as_uint(Qs[(rb[mt] + 8) * 68 + k0 + tq    ]);
                af[mt][2] = __float_as_uint(Qs[(rb[mt]    ) * 68 + k0 + tq + 4]);
                af[mt][3] = __float_as_uint(Qs[(rb[mt] + 8) * 68 + k0 + tq + 4]);
            }
#pragma unroll
            for (int nt = 0; nt < 8; nt++) {
                bf[nt][0] = __float_as_uint(Ks[(nt * 8 + g) * 68 + k0 + tq    ]);
                bf[nt][1] = __float_as_uint(Ks[(nt * 8 + g) * 68 + k0 + tq + 4]);
            }
#pragma unroll
            for (int mt = 0; mt < 2; mt++)
#pragma unroll
                for (int nt = 0; nt < 8; nt++)
                    mma8(s[mt][nt], af[mt], bf[nt]);
        }

        // mask (per kv column)
#pragma unroll
        for (int nt = 0; nt < 8; nt++) {
            const int j = nt * 8 + tq * 2;
            const int mv0 = mk[j], mv1 = mk[j + 1];
#pragma unroll
            for (int mt = 0; mt < 2; mt++) {
                if (!mv0) { s[mt][nt][0] = -1e9f; s[mt][nt][2] = -1e9f; }
                if (!mv1) { s[mt][nt][1] = -1e9f; s[mt][nt][3] = -1e9f; }
            }
        }

        // online softmax (per m-tile, rows g and g+8; reduce across quad lanes)
#pragma unroll
        for (int mt = 0; mt < 2; mt++) {
            float rm0 = -1e30f, rm1 = -1e30f;
#pragma unroll
            for (int nt = 0; nt < 8; nt++) {
                rm0 = fmaxf(rm0, fmaxf(s[mt][nt][0], s[mt][nt][1]));
                rm1 = fmaxf(rm1, fmaxf(s[mt][nt][2], s[mt][nt][3]));
            }
            rm0 = fmaxf(rm0, __shfl_xor_sync(0xffffffffu, rm0, 1));
            rm0 = fmaxf(rm0, __shfl_xor_sync(0xffffffffu, rm0, 2));
            rm1 = fmaxf(rm1, __shfl_xor_sync(0xffffffffu, rm1, 1));
            rm1 = fmaxf(rm1, __shfl_xor_sync(0xffffffffu, rm1, 2));
            const float mn0 = fmaxf(m_[mt][0], rm0), mn1 = fmaxf(m_[mt][1], rm1);
            const float al0 = __expf(m_[mt][0] - mn0), al1 = __expf(m_[mt][1] - mn1);
            float rs0 = 0.f, rs1 = 0.f;
#pragma unroll
            for (int nt = 0; nt < 8; nt++) {
                s[mt][nt][0] = __expf(s[mt][nt][0] - mn0);
                s[mt][nt][1] = __expf(s[mt][nt][1] - mn0);
                s[mt][nt][2] = __expf(s[mt][nt][2] - mn1);
                s[mt][nt][3] = __expf(s[mt][nt][3] - mn1);
                rs0 += s[mt][nt][0] + s[mt][nt][1];
                rs1 += s[mt][nt][2] + s[mt][nt][3];
            }
            rs0 += __shfl_xor_sync(0xffffffffu, rs0, 1);
            rs0 += __shfl_xor_sync(0xffffffffu, rs0, 2);
            rs1 += __shfl_xor_sync(0xffffffffu, rs1, 1);
            rs1 += __shfl_xor_sync(0xffffffffu, rs1, 2);
            l_[mt][0] = l_[mt][0] * al0 + rs0;  m_[mt][0] = mn0;
            l_[mt][1] = l_[mt][1] * al1 + rs1;  m_[mt][1] = mn1;
#pragma unroll
            for (int nt = 0; nt < 8; nt++) {
                o[mt][nt][0] *= al0; o[mt][nt][1] *= al0;
                o[mt][nt][2] *= al1; o[mt][nt][3] *= al1;
            }
        }

        // write P (tf32) to warp-private rows of Ps
#pragma unroll
        for (int mt = 0; mt < 2; mt++)
#pragma unroll
            for (int nt = 0; nt < 8; nt++) {
                const int j = nt * 8 + tq * 2;
                float2 p0 = make_float2(__uint_as_float(f2tf32(s[mt][nt][0])),
                                        __uint_as_float(f2tf32(s[mt][nt][1])));
                float2 p1 = make_float2(__uint_as_float(f2tf32(s[mt][nt][2])),
                                        __uint_as_float(f2tf32(s[mt][nt][3])));
                *(float2*)&Ps[(rb[mt]    ) * 68 + j] = p0;
                *(float2*)&Ps[(rb[mt] + 8) * 68 + j] = p1;
            }
        __syncwarp();

        // O += P @ V   (k = 64 kv, n = 64 d)
#pragma unroll
        for (int kc = 0; kc < 8; kc++) {
            const int k0 = kc * 8;
            uint32_t af[2][4], bf[8][2];
#pragma unroll
            for (int mt = 0; mt < 2; mt++) {
                af[mt][0] = __float_as_uint(Ps[(rb[mt]    ) * 68 + k0 + tq    ]);
                af[mt][1] = __float_as_uint(Ps[(rb[mt] + 8) * 68 + k0 + tq    ]);
                af[mt][2] = __float_as_uint(Ps[(rb[mt]    ) * 68 + k0 + tq + 4]);
                af[mt][3] = __float_as_uint(Ps[(rb[mt] + 8) * 68 + k0 + tq + 4]);
            }
#pragma unroll
            for (int nt = 0; nt < 8; nt++) {
                bf[nt][0] = __float_as_uint(Vs[(k0 + tq    ) * 72 + nt * 8 + g]);
                bf[nt][1] = __float_as_uint(Vs[(k0 + tq + 4) * 72 + nt * 8 + g]);
            }
#pragma unroll
            for (int mt = 0; mt < 2; mt++)
#pragma unroll
                for (int nt = 0; nt < 8; nt++)
                    mma8(o[mt][nt], af[mt], bf[nt]);
        }
    }

    // final normalize + store
#pragma unroll
    for (int mt = 0; mt < 2; mt++) {
        const float inv0 = 1.f / l_[mt][0], inv1 = 1.f / l_[mt][1];
        const int qr0 = q0 + rb[mt], qr1 = qr0 + 8;
#pragma unroll
        for (int nt = 0; nt < 8; nt++) {
            const int d = nt * 8 + tq * 2;
            float2 v0 = make_float2(o[mt][nt][0] * inv0, o[mt][nt][1] * inv0);
            float2 v1 = make_float2(o[mt][nt][2] * inv1, o[mt][nt][3] * inv1);
            *(float2*)&Og[(size_t)(b * NSEQ + qr0) * DIM + h * DH + d] = v0;
            *(float2*)&Og[(size_t)(b * NSEQ + qr1) * DIM + h * DH + d] = v1;
        }
    }
}

// ---------------------------------------------------------------------------
extern "C" void kernel_launch(void* const* d_in, const int* in_sizes, int n_in,
                              void* d_out, int out_size)
{
    const float* x1 = (const float*)d_in[0];   // feat1_query
    const float* x2 = (const float*)d_in[1];   // feat2_key_value
    const float* Wq = (const float*)d_in[2];
    const float* Wk = (const float*)d_in[3];
    const float* Wv = (const float*)d_in[4];
    const float* Wo = (const float*)d_in[5];
    const float* bo = (const float*)d_in[6];
    const int*   mk = (const int*)d_in[7];
    float* out = (float*)d_out;

    float *q, *k, *v, *a;
    cudaGetSymbolAddress((void**)&q, g_Q);
    cudaGetSymbolAddress((void**)&k, g_K);
    cudaGetSymbolAddress((void**)&v, g_V);
    cudaGetSymbolAddress((void**)&a, g_A);

    const dim3 gg(DIM / 128, MTOK / 128);   // (8, 32)
    tgemm<2><<<gg, 256>>>(x1, Wq, nullptr, q, 0.125f);
    tgemm<2><<<gg, 256>>>(x2, Wk, nullptr, k, 1.0f);
    tgemm<2><<<gg, 256>>>(x2, Wv, nullptr, v, 1.0f);

    cudaFuncSetAttribute(attn_kernel, cudaFuncAttributeMaxDynamicSharedMemorySize,
                         ATTN_SMEM_BYTES);
    attn_kernel<<<dim3(NSEQ / 128, BATCH * NH), 128, ATTN_SMEM_BYTES>>>(q, k, v, mk, a);

    tgemm<0><<<gg, 256>>>(a, Wo, bo, out, 1.0f);
}

// round 5
// speedup vs baseline: 2.6899x; 1.1075x over previous
#include <cuda_runtime.h>
#include <cstddef>
#include <cstdint>

#define BATCH 2
#define NSEQ  2048
#define DIM   1024
#define NH    16
#define DH    64
#define MTOK  (BATCH * NSEQ)   // 4096

// Scratch (allocation-free rule: __device__ globals). All [bh][s][d] layout.
__device__ float g_Q[BATCH * NH * NSEQ * DH];   // tf32 bits, pre-scaled by 1/8
__device__ float g_K[BATCH * NH * NSEQ * DH];   // tf32 bits
__device__ float g_V[BATCH * NH * NSEQ * DH];   // tf32 bits
__device__ float g_A[BATCH * NSEQ * DIM];       // attention out fp32, [b][q][h*64+d]

// ---------------------------------------------------------------------------
__device__ __forceinline__ uint32_t f2tf32(float x) {
    uint32_t y;
    asm("cvt.rna.tf32.f32 %0, %1;" : "=r"(y) : "f"(x));
    return y;
}

__device__ __forceinline__ float4 cvt4(float4 v) {
    return make_float4(__uint_as_float(f2tf32(v.x)), __uint_as_float(f2tf32(v.y)),
                       __uint_as_float(f2tf32(v.z)), __uint_as_float(f2tf32(v.w)));
}

// D += A * B, m16n8k8 tf32 (A row-major 16x8, B col-major 8x8)
__device__ __forceinline__ void mma8(float* d, const uint32_t* a, const uint32_t* b) {
    asm volatile(
        "mma.sync.aligned.m16n8k8.row.col.f32.tf32.tf32.f32 "
        "{%0,%1,%2,%3}, {%4,%5,%6,%7}, {%8,%9}, {%0,%1,%2,%3};"
        : "+f"(d[0]), "+f"(d[1]), "+f"(d[2]), "+f"(d[3])
        : "r"(a[0]), "r"(a[1]), "r"(a[2]), "r"(a[3]), "r"(b[0]), "r"(b[1]));
}

// ---------------------------------------------------------------------------
// tf32 tensor-core GEMM: C = A @ W^T. A:[M,K] row-major, W:[N,K] row-major.
// M=4096, N=K=1024. Block 128x128, BK=16 double-buffered, 8 warps (32x64 each).
// LAYOUT 0: C[m*DIM+n] = acc + bias[n]                       (fp32 out)
// LAYOUT 2: C[((b*NH+h)*NSEQ+s)*DH+d] = tf32(acc * scale)    (QKV scratch)
// ---------------------------------------------------------------------------
template <int LAYOUT>
__global__ __launch_bounds__(256)
void tgemm(const float* __restrict__ A, const float* __restrict__ W,
           const float* __restrict__ bias, float* __restrict__ C, float scale)
{
    __shared__ float As[2][128][20];
    __shared__ float Bs[2][128][20];

    const int tid = threadIdx.x;
    const int lane = tid & 31, wid = tid >> 5;
    const int g = lane >> 2, tq = lane & 3;
    const int wm = (wid & 3) * 32, wn = (wid >> 2) * 64;
    const int m0 = blockIdx.y * 128, n0 = blockIdx.x * 128;

    const int lr = tid >> 1;             // 0..127
    const int lc = (tid & 1) * 8;        // 0 or 8
    const float* Ap = A + (size_t)(m0 + lr) * DIM + lc;
    const float* Wp = W + (size_t)(n0 + lr) * DIM + lc;

    float acc[2][8][4];
#pragma unroll
    for (int mt = 0; mt < 2; mt++)
#pragma unroll
        for (int nt = 0; nt < 8; nt++)
#pragma unroll
            for (int c = 0; c < 4; c++) acc[mt][nt][c] = 0.f;

    {
        float4 a0 = *(const float4*)Ap, a1 = *(const float4*)(Ap + 4);
        float4 b0 = *(const float4*)Wp, b1 = *(const float4*)(Wp + 4);
        *(float4*)&As[0][lr][lc]     = cvt4(a0);
        *(float4*)&As[0][lr][lc + 4] = cvt4(a1);
        *(float4*)&Bs[0][lr][lc]     = cvt4(b0);
        *(float4*)&Bs[0][lr][lc + 4] = cvt4(b1);
    }
    __syncthreads();

    for (int kt = 0; kt < 64; kt++) {
        const int cur = kt & 1;
        float4 pa0, pa1, pb0, pb1;
        if (kt < 63) {
            const float* s1 = Ap + (kt + 1) * 16;
            const float* s2 = Wp + (kt + 1) * 16;
            pa0 = *(const float4*)s1; pa1 = *(const float4*)(s1 + 4);
            pb0 = *(const float4*)s2; pb1 = *(const float4*)(s2 + 4);
        }
#pragma unroll
        for (int kc = 0; kc < 2; kc++) {
            const int k0 = kc * 8;
            uint32_t af[2][4], bf[8][2];
#pragma unroll
            for (int mt = 0; mt < 2; mt++) {
                const int mb = wm + mt * 16;
                af[mt][0] = __float_as_uint(As[cur][mb + g    ][k0 + tq    ]);
                af[mt][1] = __float_as_uint(As[cur][mb + g + 8][k0 + tq    ]);
                af[mt][2] = __float_as_uint(As[cur][mb + g    ][k0 + tq + 4]);
                af[mt][3] = __float_as_uint(As[cur][mb + g + 8][k0 + tq + 4]);
            }
#pragma unroll
            for (int nt = 0; nt < 8; nt++) {
                const int nb = wn + nt * 8;
                bf[nt][0] = __float_as_uint(Bs[cur][nb + g][k0 + tq    ]);
                bf[nt][1] = __float_as_uint(Bs[cur][nb + g][k0 + tq + 4]);
            }
#pragma unroll
            for (int mt = 0; mt < 2; mt++)
#pragma unroll
                for (int nt = 0; nt < 8; nt++)
                    mma8(acc[mt][nt], af[mt], bf[nt]);
        }
        if (kt < 63) {
            *(float4*)&As[cur ^ 1][lr][lc]     = cvt4(pa0);
            *(float4*)&As[cur ^ 1][lr][lc + 4] = cvt4(pa1);
            *(float4*)&Bs[cur ^ 1][lr][lc]     = cvt4(pb0);
            *(float4*)&Bs[cur ^ 1][lr][lc + 4] = cvt4(pb1);
        }
        __syncthreads();
    }

#pragma unroll
    for (int mt = 0; mt < 2; mt++) {
        const int r0 = m0 + wm + mt * 16 + g;
        const int r1 = r0 + 8;
#pragma unroll
        for (int nt = 0; nt < 8; nt++) {
            const int n = n0 + wn + nt * 8 + tq * 2;
            if (LAYOUT == 0) {
                const float b0v = bias[n], b1v = bias[n + 1];
                float2 v0 = make_float2(acc[mt][nt][0] + b0v, acc[mt][nt][1] + b1v);
                float2 v1 = make_float2(acc[mt][nt][2] + b0v, acc[mt][nt][3] + b1v);
                *(float2*)&C[(size_t)r0 * DIM + n] = v0;
                *(float2*)&C[(size_t)r1 * DIM + n] = v1;
            } else {
                const int h = n >> 6, d = n & 63;
                const int b0i = r0 >> 11, s0 = r0 & (NSEQ - 1);
                const int b1i = r1 >> 11, s1 = r1 & (NSEQ - 1);
                float2 v0 = make_float2(
                    __uint_as_float(f2tf32(acc[mt][nt][0] * scale)),
                    __uint_as_float(f2tf32(acc[mt][nt][1] * scale)));
                float2 v1 = make_float2(
                    __uint_as_float(f2tf32(acc[mt][nt][2] * scale)),
                    __uint_as_float(f2tf32(acc[mt][nt][3] * scale)));
                *(float2*)&C[((size_t)(b0i * NH + h) * NSEQ + s0) * DH + d] = v0;
                *(float2*)&C[((size_t)(b1i * NH + h) * NSEQ + s1) * DH + d] = v1;
            }
        }
    }
}

// ---------------------------------------------------------------------------
// Flash attention on tensor cores. Bq=128 (4 warps x 2 m-tiles x 16 rows),
// Bk=64, Dh=64. Q pre-scaled by 1/8; Q/K/V tf32 bits in [bh][s][d].
// Q fragments hoisted to registers; P overlays the Q staging buffer.
// ---------------------------------------------------------------------------
#define AQP 0                   // Q staging, then P: [128][68]
#define AK  8704
#define AV  13056               // Ks: 64*68
#define AM  17664               // Vs: 64*72
#define ATTN_SMEM_BYTES ((17664 + 64) * 4)   // 70912

__global__ __launch_bounds__(128)
void attn_kernel(const float* __restrict__ Qg, const float* __restrict__ Kg,
                 const float* __restrict__ Vg, const int* __restrict__ mask,
                 float* __restrict__ Og)
{
    extern __shared__ float sm[];
    float* QPs = sm + AQP;  // [128][68]  (Q staging -> P)
    float* Ks  = sm + AK;   // [64][68]
    float* Vs  = sm + AV;   // [64][72]
    int*   mk  = (int*)(sm + AM);

    const int tid = threadIdx.x;
    const int lane = tid & 31, w = tid >> 5;
    const int g = lane >> 2, tq = lane & 3;
    const int bh = blockIdx.y;
    const int b = bh >> 4, h = bh & 15;
    const int q0 = blockIdx.x * 128;

    // stage Q tile (contiguous 128x64 block) into padded smem
    {
        const float* Qb = Qg + ((size_t)bh * NSEQ + q0) * DH;
#pragma unroll
        for (int it = 0; it < 16; it++) {
            int j = it * 128 + tid;                       // float4 index
            *(float4*)&QPs[(j >> 4) * 68 + (j & 15) * 4] = *(const float4*)(Qb + j * 4);
        }
    }
    __syncthreads();

    const int rb[2] = { w * 32 + g, w * 32 + 16 + g };    // base rows per m-tile

    // hoist Q fragments (loop-invariant) into registers; QPs rows rb[*] are
    // warp-private, so the buffer can be reused for P afterwards.
    uint32_t qf[2][8][4];
#pragma unroll
    for (int mt = 0; mt < 2; mt++)
#pragma unroll
        for (int kc = 0; kc < 8; kc++) {
            const int k0 = kc * 8;
            qf[mt][kc][0] = __float_as_uint(QPs[(rb[mt]    ) * 68 + k0 + tq    ]);
            qf[mt][kc][1] = __float_as_uint(QPs[(rb[mt] + 8) * 68 + k0 + tq    ]);
            qf[mt][kc][2] = __float_as_uint(QPs[(rb[mt]    ) * 68 + k0 + tq + 4]);
            qf[mt][kc][3] = __float_as_uint(QPs[(rb[mt] + 8) * 68 + k0 + tq + 4]);
        }

    float m_[2][2], l_[2][2], o[2][8][4];
#pragma unroll
    for (int mt = 0; mt < 2; mt++) {
        m_[mt][0] = -1e30f; m_[mt][1] = -1e30f;
        l_[mt][0] = 0.f;    l_[mt][1] = 0.f;
#pragma unroll
        for (int nt = 0; nt < 8; nt++)
#pragma unroll
            for (int c = 0; c < 4; c++) o[mt][nt][c] = 0.f;
    }

    for (int t = 0; t < NSEQ / 64; t++) {
        const int kv0 = t * 64;
        __syncthreads();
        {
            const float* Kb = Kg + ((size_t)bh * NSEQ + kv0) * DH;
            const float* Vb = Vg + ((size_t)bh * NSEQ + kv0) * DH;
#pragma unroll
            for (int it = 0; it < 8; it++) {
                int j = it * 128 + tid;                   // float4 index (64*16)
                *(float4*)&Ks[(j >> 4) * 68 + (j & 15) * 4] = *(const float4*)(Kb + j * 4);
                *(float4*)&Vs[(j >> 4) * 72 + (j & 15) * 4] = *(const float4*)(Vb + j * 4);
            }
            if (tid < 64) mk[tid] = mask[b * NSEQ + kv0 + tid];
        }
        __syncthreads();

        // S = Q @ K^T  (2 x 16 q-rows per warp x 64 kv)
        float s[2][8][4];
#pragma unroll
        for (int mt = 0; mt < 2; mt++)
#pragma unroll
            for (int nt = 0; nt < 8; nt++)
#pragma unroll
                for (int c = 0; c < 4; c++) s[mt][nt][c] = 0.f;

#pragma unroll
        for (int kc = 0; kc < 8; kc++) {
            const int k0 = kc * 8;
            uint32_t bf[8][2];
#pragma unroll
            for (int nt = 0; nt < 8; nt++) {
                bf[nt][0] = __float_as_uint(Ks[(nt * 8 + g) * 68 + k0 + tq    ]);
                bf[nt][1] = __float_as_uint(Ks[(nt * 8 + g) * 68 + k0 + tq + 4]);
            }
#pragma unroll
            for (int mt = 0; mt < 2; mt++)
#pragma unroll
                for (int nt = 0; nt < 8; nt++)
                    mma8(s[mt][nt], qf[mt][kc], bf[nt]);
        }

        // mask (per kv column)
#pragma unroll
        for (int nt = 0; nt < 8; nt++) {
            const int j = nt * 8 + tq * 2;
            const int mv0 = mk[j], mv1 = mk[j + 1];
#pragma unroll
            for (int mt = 0; mt < 2; mt++) {
                if (!mv0) { s[mt][nt][0] = -1e9f; s[mt][nt][2] = -1e9f; }
                if (!mv1) { s[mt][nt][1] = -1e9f; s[mt][nt][3] = -1e9f; }
            }
        }

        // online softmax (per m-tile, rows g and g+8; reduce across quad lanes)
#pragma unroll
        for (int mt = 0; mt < 2; mt++) {
            float rm0 = -1e30f, rm1 = -1e30f;
#pragma unroll
            for (int nt = 0; nt < 8; nt++) {
                rm0 = fmaxf(rm0, fmaxf(s[mt][nt][0], s[mt][nt][1]));
                rm1 = fmaxf(rm1, fmaxf(s[mt][nt][2], s[mt][nt][3]));
            }
            rm0 = fmaxf(rm0, __shfl_xor_sync(0xffffffffu, rm0, 1));
            rm0 = fmaxf(rm0, __shfl_xor_sync(0xffffffffu, rm0, 2));
            rm1 = fmaxf(rm1, __shfl_xor_sync(0xffffffffu, rm1, 1));
            rm1 = fmaxf(rm1, __shfl_xor_sync(0xffffffffu, rm1, 2));
            const float mn0 = fmaxf(m_[mt][0], rm0), mn1 = fmaxf(m_[mt][1], rm1);
            const float al0 = __expf(m_[mt][0] - mn0), al1 = __expf(m_[mt][1] - mn1);
            float rs0 = 0.f, rs1 = 0.f;
#pragma unroll
            for (int nt = 0; nt < 8; nt++) {
                s[mt][nt][0] = __expf(s[mt][nt][0] - mn0);
                s[mt][nt][1] = __expf(s[mt][nt][1] - mn0);
                s[mt][nt][2] = __expf(s[mt][nt][2] - mn1);
                s[mt][nt][3] = __expf(s[mt][nt][3] - mn1);
                rs0 += s[mt][nt][0] + s[mt][nt][1];
                rs1 += s[mt][nt][2] + s[mt][nt][3];
            }
            rs0 += __shfl_xor_sync(0xffffffffu, rs0, 1);
            rs0 += __shfl_xor_sync(0xffffffffu, rs0, 2);
            rs1 += __shfl_xor_sync(0xffffffffu, rs1, 1);
            rs1 += __shfl_xor_sync(0xffffffffu, rs1, 2);
            l_[mt][0] = l_[mt][0] * al0 + rs0;  m_[mt][0] = mn0;
            l_[mt][1] = l_[mt][1] * al1 + rs1;  m_[mt][1] = mn1;
#pragma unroll
            for (int nt = 0; nt < 8; nt++) {
                o[mt][nt][0] *= al0; o[mt][nt][1] *= al0;
                o[mt][nt][2] *= al1; o[mt][nt][3] *= al1;
            }
        }

        // write P (tf32) to warp-private rows of QPs
#pragma unroll
        for (int mt = 0; mt < 2; mt++)
#pragma unroll
            for (int nt = 0; nt < 8; nt++) {
                const int j = nt * 8 + tq * 2;
                float2 p0 = make_float2(__uint_as_float(f2tf32(s[mt][nt][0])),
                                        __uint_as_float(f2tf32(s[mt][nt][1])));
                float2 p1 = make_float2(__uint_as_float(f2tf32(s[mt][nt][2])),
                                        __uint_as_float(f2tf32(s[mt][nt][3])));
                *(float2*)&QPs[(rb[mt]    ) * 68 + j] = p0;
                *(float2*)&QPs[(rb[mt] + 8) * 68 + j] = p1;
            }
        __syncwarp();

        // O += P @ V   (k = 64 kv, n = 64 d)
#pragma unroll
        for (int kc = 0; kc < 8; kc++) {
            const int k0 = kc * 8;
            uint32_t af[2][4], bf[8][2];
#pragma unroll
            for (int mt = 0; mt < 2; mt++) {
                af[mt][0] = __float_as_uint(QPs[(rb[mt]    ) * 68 + k0 + tq    ]);
                af[mt][1] = __float_as_uint(QPs[(rb[mt] + 8) * 68 + k0 + tq    ]);
                af[mt][2] = __float_as_uint(QPs[(rb[mt]    ) * 68 + k0 + tq + 4]);
                af[mt][3] = __float_as_uint(QPs[(rb[mt] + 8) * 68 + k0 + tq + 4]);
            }
#pragma unroll
            for (int nt = 0; nt < 8; nt++) {
                bf[nt][0] = __float_as_uint(Vs[(k0 + tq    ) * 72 + nt * 8 + g]);
                bf[nt][1] = __float_as_uint(Vs[(k0 + tq + 4) * 72 + nt * 8 + g]);
            }
#pragma unroll
            for (int mt = 0; mt < 2; mt++)
#pragma unroll
                for (int nt = 0; nt < 8; nt++)
                    mma8(o[mt][nt], af[mt], bf[nt]);
        }
    }

    // final normalize + store
#pragma unroll
    for (int mt = 0; mt < 2; mt++) {
        const float inv0 = 1.f / l_[mt][0], inv1 = 1.f / l_[mt][1];
        const int qr0 = q0 + rb[mt], qr1 = qr0 + 8;
#pragma unroll
        for (int nt = 0; nt < 8; nt++) {
            const int d = nt * 8 + tq * 2;
            float2 v0 = make_float2(o[mt][nt][0] * inv0, o[mt][nt][1] * inv0);
            float2 v1 = make_float2(o[mt][nt][2] * inv1, o[mt][nt][3] * inv1);
            *(float2*)&Og[(size_t)(b * NSEQ + qr0) * DIM + h * DH + d] = v0;
            *(float2*)&Og[(size_t)(b * NSEQ + qr1) * DIM + h * DH + d] = v1;
        }
    }
}

// ---------------------------------------------------------------------------
extern "C" void kernel_launch(void* const* d_in, const int* in_sizes, int n_in,
                              void* d_out, int out_size)
{
    const float* x1 = (const float*)d_in[0];   // feat1_query
    const float* x2 = (const float*)d_in[1];   // feat2_key_value
    const float* Wq = (const float*)d_in[2];
    const float* Wk = (const float*)d_in[3];
    const float* Wv = (const float*)d_in[4];
    const float* Wo = (const float*)d_in[5];
    const float* bo = (const float*)d_in[6];
    const int*   mk = (const int*)d_in[7];
    float* out = (float*)d_out;

    float *q, *k, *v, *a;
    cudaGetSymbolAddress((void**)&q, g_Q);
    cudaGetSymbolAddress((void**)&k, g_K);
    cudaGetSymbolAddress((void**)&v, g_V);
    cudaGetSymbolAddress((void**)&a, g_A);

    const dim3 gg(DIM / 128, MTOK / 128);   // (8, 32)
    tgemm<2><<<gg, 256>>>(x1, Wq, nullptr, q, 0.125f);
    tgemm<2><<<gg, 256>>>(x2, Wk, nullptr, k, 1.0f);
    tgemm<2><<<gg, 256>>>(x2, Wv, nullptr, v, 1.0f);

    cudaFuncSetAttribute(attn_kernel, cudaFuncAttributeMaxDynamicSharedMemorySize,
                         ATTN_SMEM_BYTES);
    attn_kernel<<<dim3(NSEQ / 128, BATCH * NH), 128, ATTN_SMEM_BYTES>>>(q, k, v, mk, a);

    tgemm<0><<<gg, 256>>>(a, Wo, bo, out, 1.0f);
}

// round 7
// speedup vs baseline: 3.0161x; 1.1213x over previous
#include <cuda_runtime.h>
#include <cstddef>
#include <cstdint>

#define BATCH 2
#define NSEQ  2048
#define DIM   1024
#define NH    16
#define DH    64
#define MTOK  (BATCH * NSEQ)   // 4096

// Scratch (allocation-free rule: __device__ globals). All [bh][s][d] layout.
__device__ float g_Q[BATCH * NH * NSEQ * DH];   // tf32 bits, pre-scaled by 1/8
__device__ float g_K[BATCH * NH * NSEQ * DH];   // tf32 bits
__device__ float g_V[BATCH * NH * NSEQ * DH];   // tf32 bits
__device__ float g_A[BATCH * NSEQ * DIM];       // attention out fp32, [b][q][h*64+d]

// ---------------------------------------------------------------------------
__device__ __forceinline__ uint32_t f2tf32(float x) {
    uint32_t y;
    asm("cvt.rna.tf32.f32 %0, %1;" : "=r"(y) : "f"(x));
    return y;
}

__device__ __forceinline__ float4 cvt4(float4 v) {
    return make_float4(__uint_as_float(f2tf32(v.x)), __uint_as_float(f2tf32(v.y)),
                       __uint_as_float(f2tf32(v.z)), __uint_as_float(f2tf32(v.w)));
}

__device__ __forceinline__ uint32_t cvta_smem(const void* p) {
    uint32_t a;
    asm("{ .reg .u64 t; cvta.to.shared.u64 t, %1; cvt.u32.u64 %0, t; }"
        : "=r"(a) : "l"(p));
    return a;
}

// ldmatrix x4: four 8x8 b16 matrices == four 8x4 b32 (tf32) fragments
__device__ __forceinline__ void ldsm4(uint32_t* r, uint32_t addr) {
    asm volatile("ldmatrix.sync.aligned.m8n8.x4.shared.b16 {%0,%1,%2,%3}, [%4];"
                 : "=r"(r[0]), "=r"(r[1]), "=r"(r[2]), "=r"(r[3]) : "r"(addr));
}

// D += A * B, m16n8k8 tf32 (A row-major 16x8, B col-major 8x8)
__device__ __forceinline__ void mma8(float* d, const uint32_t* a, const uint32_t* b) {
    asm volatile(
        "mma.sync.aligned.m16n8k8.row.col.f32.tf32.tf32.f32 "
        "{%0,%1,%2,%3}, {%4,%5,%6,%7}, {%8,%9}, {%0,%1,%2,%3};"
        : "+f"(d[0]), "+f"(d[1]), "+f"(d[2]), "+f"(d[3])
        : "r"(a[0]), "r"(a[1]), "r"(a[2]), "r"(a[3]), "r"(b[0]), "r"(b[1]));
}

// ---------------------------------------------------------------------------
// tf32 tensor-core GEMM: C = A @ W^T. A:[M,K] row-major, W:[N,K] row-major.
// M=4096, N=K=1024. Block 128x128, BK=16 double-buffered, 8 warps (32x64 each).
// Fragment loads via ldmatrix.x4.
// LAYOUT 0: C[m*DIM+n] = acc + bias[n]                       (fp32 out)
// LAYOUT 2: C[((b*NH+h)*NSEQ+s)*DH+d] = tf32(acc * scale)    (QKV scratch)
// ---------------------------------------------------------------------------
template <int LAYOUT>
__global__ __launch_bounds__(256)
void tgemm(const float* __restrict__ A, const float* __restrict__ W,
           const float* __restrict__ bias, float* __restrict__ C, float scale)
{
    __shared__ float As[2][128][20];
    __shared__ float Bs[2][128][20];

    const int tid = threadIdx.x;
    const int lane = tid & 31, wid = tid >> 5;
    const int g = lane >> 2, tq = lane & 3;
    const int wm = (wid & 3) * 32, wn = (wid >> 2) * 64;
    const int m0 = blockIdx.y * 128, n0 = blockIdx.x * 128;

    // ldmatrix per-lane row/col mapping
    const int lrA = lane & 15;                         // A: +wm +mt*16
    const int lcA = (lane >> 4) * 4;                   // A: +kc*8
    const int lrB = (lane & 7) + ((lane >> 4) << 3);   // B: +wn +p*16
    const int lcB = ((lane >> 3) & 1) * 4;             // B: +kc*8

    const uint32_t As_b = cvta_smem(&As[0][0][0]);
    const uint32_t Bs_b = cvta_smem(&Bs[0][0][0]);
    const uint32_t aA = As_b + (uint32_t)(wm + lrA) * 80u + (uint32_t)lcA * 4u;
    const uint32_t aB = Bs_b + (uint32_t)(wn + lrB) * 80u + (uint32_t)lcB * 4u;

    const int lr = tid >> 1;             // 0..127
    const int lc = (tid & 1) * 8;        // 0 or 8
    const float* Ap = A + (size_t)(m0 + lr) * DIM + lc;
    const float* Wp = W + (size_t)(n0 + lr) * DIM + lc;

    float acc[2][8][4];
#pragma unroll
    for (int mt = 0; mt < 2; mt++)
#pragma unroll
        for (int nt = 0; nt < 8; nt++)
#pragma unroll
            for (int c = 0; c < 4; c++) acc[mt][nt][c] = 0.f;

    {
        float4 a0 = *(const float4*)Ap, a1 = *(const float4*)(Ap + 4);
        float4 b0 = *(const float4*)Wp, b1 = *(const float4*)(Wp + 4);
        *(float4*)&As[0][lr][lc]     = cvt4(a0);
        *(float4*)&As[0][lr][lc + 4] = cvt4(a1);
        *(float4*)&Bs[0][lr][lc]     = cvt4(b0);
        *(float4*)&Bs[0][lr][lc + 4] = cvt4(b1);
    }
    __syncthreads();

    for (int kt = 0; kt < 64; kt++) {
        const uint32_t bo = (kt & 1) ? 10240u : 0u;    // buffer byte offset
        float4 pa0, pa1, pb0, pb1;
        if (kt < 63) {
            const float* s1 = Ap + (kt + 1) * 16;
            const float* s2 = Wp + (kt + 1) * 16;
            pa0 = *(const float4*)s1; pa1 = *(const float4*)(s1 + 4);
            pb0 = *(const float4*)s2; pb1 = *(const float4*)(s2 + 4);
        }
#pragma unroll
        for (int kc = 0; kc < 2; kc++) {
            uint32_t af[2][4], bf[4][4];
            ldsm4(af[0], aA + bo + kc * 32u);
            ldsm4(af[1], aA + bo + 1280u + kc * 32u);
#pragma unroll
            for (int p = 0; p < 4; p++)
                ldsm4(bf[p], aB + bo + (uint32_t)p * 1280u + kc * 32u);
#pragma unroll
            for (int mt = 0; mt < 2; mt++)
#pragma unroll
                for (int p = 0; p < 4; p++) {
                    mma8(acc[mt][2 * p],     af[mt], &bf[p][0]);
                    mma8(acc[mt][2 * p + 1], af[mt], &bf[p][2]);
                }
        }
        if (kt < 63) {
            const uint32_t nxt = (kt & 1) ^ 1;
            *(float4*)&As[nxt][lr][lc]     = cvt4(pa0);
            *(float4*)&As[nxt][lr][lc + 4] = cvt4(pa1);
            *(float4*)&Bs[nxt][lr][lc]     = cvt4(pb0);
            *(float4*)&Bs[nxt][lr][lc + 4] = cvt4(pb1);
        }
        __syncthreads();
    }

#pragma unroll
    for (int mt = 0; mt < 2; mt++) {
        const int r0 = m0 + wm + mt * 16 + g;
        const int r1 = r0 + 8;
#pragma unroll
        for (int nt = 0; nt < 8; nt++) {
            const int n = n0 + wn + nt * 8 + tq * 2;
            if (LAYOUT == 0) {
                const float b0v = bias[n], b1v = bias[n + 1];
                float2 v0 = make_float2(acc[mt][nt][0] + b0v, acc[mt][nt][1] + b1v);
                float2 v1 = make_float2(acc[mt][nt][2] + b0v, acc[mt][nt][3] + b1v);
                *(float2*)&C[(size_t)r0 * DIM + n] = v0;
                *(float2*)&C[(size_t)r1 * DIM + n] = v1;
            } else {
                const int h = n >> 6, d = n & 63;
                const int b0i = r0 >> 11, s0 = r0 & (NSEQ - 1);
                const int b1i = r1 >> 11, s1 = r1 & (NSEQ - 1);
                float2 v0 = make_float2(
                    __uint_as_float(f2tf32(acc[mt][nt][0] * scale)),
                    __uint_as_float(f2tf32(acc[mt][nt][1] * scale)));
                float2 v1 = make_float2(
                    __uint_as_float(f2tf32(acc[mt][nt][2] * scale)),
                    __uint_as_float(f2tf32(acc[mt][nt][3] * scale)));
                *(float2*)&C[((size_t)(b0i * NH + h) * NSEQ + s0) * DH + d] = v0;
                *(float2*)&C[((size_t)(b1i * NH + h) * NSEQ + s1) * DH + d] = v1;
            }
        }
    }
}

// ---------------------------------------------------------------------------
// Flash attention on tensor cores. Bq=128 (4 warps x 2 m-tiles x 16 rows),
// Bk=64, Dh=64. Q pre-scaled by 1/8; Q/K/V tf32 bits in [bh][s][d].
// Q fragments hoisted via ldmatrix; K/P fragments via ldmatrix; P overlays Q.
// ---------------------------------------------------------------------------
#define AQP 0                   // Q staging, then P: [128][68]
#define AK  8704
#define AV  13056               // Ks: 64*68
#define AM  17664               // Vs: 64*72
#define ATTN_SMEM_BYTES ((17664 + 64) * 4)   // 70912

__global__ __launch_bounds__(128)
void attn_kernel(const float* __restrict__ Qg, const float* __restrict__ Kg,
                 const float* __restrict__ Vg, const int* __restrict__ mask,
                 float* __restrict__ Og)
{
    extern __shared__ float sm[];
    float* QPs = sm + AQP;  // [128][68]  (Q staging -> P)
    float* Ks  = sm + AK;   // [64][68]
    float* Vs  = sm + AV;   // [64][72]
    int*   mk  = (int*)(sm + AM);

    const int tid = threadIdx.x;
    const int lane = tid & 31, w = tid >> 5;
    const int g = lane >> 2, tq = lane & 3;
    const int bh = blockIdx.y;
    const int b = bh >> 4, h = bh & 15;
    const int q0 = blockIdx.x * 128;

    // ldmatrix per-lane mappings (row stride 68 floats = 272 bytes)
    const int lrA = lane & 15;
    const int lcA = (lane >> 4) * 4;
    const int lrB = (lane & 7) + ((lane >> 4) << 3);
    const int lcB = ((lane >> 3) & 1) * 4;
    const uint32_t pA = cvta_smem(QPs) + (uint32_t)(w * 32 + lrA) * 272u +
                        (uint32_t)lcA * 4u;                   // +mt*4352 +kc*32
    const uint32_t pK = cvta_smem(Ks) + (uint32_t)lrB * 272u +
                        (uint32_t)lcB * 4u;                   // +p*4352 +kc*32

    // stage Q tile (contiguous 128x64 block) into padded smem
    {
        const float* Qb = Qg + ((size_t)bh * NSEQ + q0) * DH;
#pragma unroll
        for (int it = 0; it < 16; it++) {
            int j = it * 128 + tid;                       // float4 index
            *(float4*)&QPs[(j >> 4) * 68 + (j & 15) * 4] = *(const float4*)(Qb + j * 4);
        }
    }
    __syncthreads();

    const int rb[2] = { w * 32 + g, w * 32 + 16 + g };    // base rows per m-tile

    // hoist Q fragments (loop-invariant) into registers via ldmatrix
    uint32_t qf[2][8][4];
#pragma unroll
    for (int mt = 0; mt < 2; mt++)
#pragma unroll
        for (int kc = 0; kc < 8; kc++)
            ldsm4(qf[mt][kc], pA + (uint32_t)mt * 4352u + (uint32_t)kc * 32u);

    float m_[2][2], l_[2][2], o[2][8][4];
#pragma unroll
    for (int mt = 0; mt < 2; mt++) {
        m_[mt][0] = -1e30f; m_[mt][1] = -1e30f;
        l_[mt][0] = 0.f;    l_[mt][1] = 0.f;
#pragma unroll
        for (int nt = 0; nt < 8; nt++)
#pragma unroll
            for (int c = 0; c < 4; c++) o[mt][nt][c] = 0.f;
    }

    for (int t = 0; t < NSEQ / 64; t++) {
        const int kv0 = t * 64;
        __syncthreads();
        {
            const float* Kb = Kg + ((size_t)bh * NSEQ + kv0) * DH;
            const float* Vb = Vg + ((size_t)bh * NSEQ + kv0) * DH;
#pragma unroll
            for (int it = 0; it < 8; it++) {
                int j = it * 128 + tid;                   // float4 index (64*16)
                *(float4*)&Ks[(j >> 4) * 68 + (j & 15) * 4] = *(const float4*)(Kb + j * 4);
                *(float4*)&Vs[(j >> 4) * 72 + (j & 15) * 4] = *(const float4*)(Vb + j * 4);
            }
            if (tid < 64) mk[tid] = mask[b * NSEQ + kv0 + tid];
        }
        __syncthreads();

        // S = Q @ K^T  (2 x 16 q-rows per warp x 64 kv)
        float s[2][8][4];
#pragma unroll
        for (int mt = 0; mt < 2; mt++)
#pragma unroll
            for (int nt = 0; nt < 8; nt++)
#pragma unroll
                for (int c = 0; c < 4; c++) s[mt][nt][c] = 0.f;

#pragma unroll
        for (int kc = 0; kc < 8; kc++) {
            uint32_t kf[4][4];
#pragma unroll
            for (int p = 0; p < 4; p++)
                ldsm4(kf[p], pK + (uint32_t)p * 4352u + (uint32_t)kc * 32u);
#pragma unroll
            for (int mt = 0; mt < 2; mt++)
#pragma unroll
                for (int p = 0; p < 4; p++) {
                    mma8(s[mt][2 * p],     qf[mt][kc], &kf[p][0]);
                    mma8(s[mt][2 * p + 1], qf[mt][kc], &kf[p][2]);
                }
        }

        // mask (per kv column)
#pragma unroll
        for (int nt = 0; nt < 8; nt++) {
            const int j = nt * 8 + tq * 2;
            const int mv0 = mk[j], mv1 = mk[j + 1];
#pragma unroll
            for (int mt = 0; mt < 2; mt++) {
                if (!mv0) { s[mt][nt][0] = -1e9f; s[mt][nt][2] = -1e9f; }
                if (!mv1) { s[mt][nt][1] = -1e9f; s[mt][nt][3] = -1e9f; }
            }
        }

        // online softmax (per m-tile, rows g and g+8; reduce across quad lanes)
#pragma unroll
        for (int mt = 0; mt < 2; mt++) {
            float rm0 = -1e30f, rm1 = -1e30f;
#pragma unroll
            for (int nt = 0; nt < 8; nt++) {
                rm0 = fmaxf(rm0, fmaxf(s[mt][nt][0], s[mt][nt][1]));
                rm1 = fmaxf(rm1, fmaxf(s[mt][nt][2], s[mt][nt][3]));
            }
            rm0 = fmaxf(rm0, __shfl_xor_sync(0xffffffffu, rm0, 1));
            rm0 = fmaxf(rm0, __shfl_xor_sync(0xffffffffu, rm0, 2));
            rm1 = fmaxf(rm1, __shfl_xor_sync(0xffffffffu, rm1, 1));
            rm1 = fmaxf(rm1, __shfl_xor_sync(0xffffffffu, rm1, 2));
            const float mn0 = fmaxf(m_[mt][0], rm0), mn1 = fmaxf(m_[mt][1], rm1);
            const float al0 = __expf(m_[mt][0] - mn0), al1 = __expf(m_[mt][1] - mn1);
            float rs0 = 0.f, rs1 = 0.f;
#pragma unroll
            for (int nt = 0; nt < 8; nt++) {
                s[mt][nt][0] = __expf(s[mt][nt][0] - mn0);
                s[mt][nt][1] = __expf(s[mt][nt][1] - mn0);
                s[mt][nt][2] = __expf(s[mt][nt][2] - mn1);
                s[mt][nt][3] = __expf(s[mt][nt][3] - mn1);
                rs0 += s[mt][nt][0] + s[mt][nt][1];
                rs1 += s[mt][nt][2] + s[mt][nt][3];
            }
            rs0 += __shfl_xor_sync(0xffffffffu, rs0, 1);
            rs0 += __shfl_xor_sync(0xffffffffu, rs0, 2);
            rs1 += __shfl_xor_sync(0xffffffffu, rs1, 1);
            rs1 += __shfl_xor_sync(0xffffffffu, rs1, 2);
            l_[mt][0] = l_[mt][0] * al0 + rs0;  m_[mt][0] = mn0;
            l_[mt][1] = l_[mt][1] * al1 + rs1;  m_[mt][1] = mn1;
#pragma unroll
            for (int nt = 0; nt < 8; nt++) {
                o[mt][nt][0] *= al0; o[mt][nt][1] *= al0;
                o[mt][nt][2] *= al1; o[mt][nt][3] *= al1;
            }
        }

        // write P (tf32) to warp-private rows of QPs
#pragma unroll
        for (int mt = 0; mt < 2; mt++)
#pragma unroll
            for (int nt = 0; nt < 8; nt++) {
                const int j = nt * 8 + tq * 2;
                float2 p0 = make_float2(__uint_as_float(f2tf32(s[mt][nt][0])),
                                        __uint_as_float(f2tf32(s[mt][nt][1])));
                float2 p1 = make_float2(__uint_as_float(f2tf32(s[mt][nt][2])),
                                        __uint_as_float(f2tf32(s[mt][nt][3])));
                *(float2*)&QPs[(rb[mt]    ) * 68 + j] = p0;
                *(float2*)&QPs[(rb[mt] + 8) * 68 + j] = p1;
            }
        __syncwarp();

        // O += P @ V   (k = 64 kv, n = 64 d)
#pragma unroll
        for (int kc = 0; kc < 8; kc++) {
            const int k0 = kc * 8;
            uint32_t af[2][4], bf[8][2];
            ldsm4(af[0], pA + (uint32_t)kc * 32u);
            ldsm4(af[1], pA + 4352u + (uint32_t)kc * 32u);
#pragma unroll
            for (int nt = 0; nt < 8; nt++) {
                bf[nt][0] = __float_as_uint(Vs[(k0 + tq    ) * 72 + nt * 8 + g]);
                bf[nt][1] = __float_as_uint(Vs[(k0 + tq + 4) * 72 + nt * 8 + g]);
            }
#pragma unroll
            for (int mt = 0; mt < 2; mt++)
#pragma unroll
                for (int nt = 0; nt < 8; nt++)
                    mma8(o[mt][nt], af[mt], bf[nt]);
        }
    }

    // final normalize + store
#pragma unroll
    for (int mt = 0; mt < 2; mt++) {
        const float inv0 = 1.f / l_[mt][0], inv1 = 1.f / l_[mt][1];
        const int qr0 = q0 + rb[mt], qr1 = qr0 + 8;
#pragma unroll
        for (int nt = 0; nt < 8; nt++) {
            const int d = nt * 8 + tq * 2;
            float2 v0 = make_float2(o[mt][nt][0] * inv0, o[mt][nt][1] * inv0);
            float2 v1 = make_float2(o[mt][nt][2] * inv1, o[mt][nt][3] * inv1);
            *(float2*)&Og[(size_t)(b * NSEQ + qr0) * DIM + h * DH + d] = v0;
            *(float2*)&Og[(size_t)(b * NSEQ + qr1) * DIM + h * DH + d] = v1;
        }
    }
}

// ---------------------------------------------------------------------------
extern "C" void kernel_launch(void* const* d_in, const int* in_sizes, int n_in,
                              void* d_out, int out_size)
{
    const float* x1 = (const float*)d_in[0];   // feat1_query
    const float* x2 = (const float*)d_in[1];   // feat2_key_value
    const float* Wq = (const float*)d_in[2];
    const float* Wk = (const float*)d_in[3];
    const float* Wv = (const float*)d_in[4];
    const float* Wo = (const float*)d_in[5];
    const float* bo = (const float*)d_in[6];
    const int*   mk = (const int*)d_in[7];
    float* out = (float*)d_out;

    float *q, *k, *v, *a;
    cudaGetSymbolAddress((void**)&q, g_Q);
    cudaGetSymbolAddress((void**)&k, g_K);
    cudaGetSymbolAddress((void**)&v, g_V);
    cudaGetSymbolAddress((void**)&a, g_A);

    const dim3 gg(DIM / 128, MTOK / 128);   // (8, 32)
    tgemm<2><<<gg, 256>>>(x1, Wq, nullptr, q, 0.125f);
    tgemm<2><<<gg, 256>>>(x2, Wk, nullptr, k, 1.0f);
    tgemm<2><<<gg, 256>>>(x2, Wv, nullptr, v, 1.0f);

    cudaFuncSetAttribute(attn_kernel, cudaFuncAttributeMaxDynamicSharedMemorySize,
                         ATTN_SMEM_BYTES);
    attn_kernel<<<dim3(NSEQ / 128, BATCH * NH), 128, ATTN_SMEM_BYTES>>>(q, k, v, mk, a);

    tgemm<0><<<gg, 256>>>(a, Wo, bo, out, 1.0f);
}